// round 1
// baseline (speedup 1.0000x reference)
#include <cuda_runtime.h>
#include <cstdint>
#include <cstddef>

#define NPOI 4096
#define DD   64
#define NB   8
#define DAYS 4
#define LL   64
#define NDROWS (NB*DAYS)   // 32
#define NPOS   (DAYS*LL)   // 256 gathered positions per sample
#define NINT   101
#define KC     4           // K-chunks for layer-2 GEMM

typedef unsigned long long u64;

// ---------------- scratch (device globals: allocation-free per harness rules) ----
__device__ __align__(16) unsigned char g_bk[(size_t)NPOI * NPOI];   // 16 MB bucket matrix
__device__ unsigned char g_diag[NPOI];
__device__ int   g_histT[NINT * NPOI];       // transposed row-bucket histogram
__device__ float g_lut[NB * NINT];           // per-sample LUT: cnt[k]/63
__device__ float g_invdeg[NB * NPOI];
__device__ int   g_order[NDROWS];
__device__ int   g_rows[NB * NPOS];          // gathered poi row indices (0-based)
__device__ float g_Y0[(size_t)NB * NPOI * DD];  // poi_emb / deg
__device__ float g_L1[(size_t)NB * NPOI * DD];  // layer-1 (tanh)
__device__ float g_Y1[(size_t)NB * NPOI * DD];  // layer1 / deg
__device__ float g_part[(size_t)KC * NB * NPOS * DD]; // layer-2 K-split partials

// ---------------- packed fp32x2 helpers (FFMA2 only reachable via PTX) ----------
__device__ __forceinline__ u64 pack2(float v) {
    u64 r; unsigned int u = __float_as_uint(v);
    asm("mov.b64 %0, {%1, %1};" : "=l"(r) : "r"(u));
    return r;
}
__device__ __forceinline__ u64 ffma2(u64 a, u64 b, u64 c) {
    u64 d; asm("fma.rn.f32x2 %0, %1, %2, %3;" : "=l"(d) : "l"(a), "l"(b), "l"(c));
    return d;
}
__device__ __forceinline__ float2 unpack2(u64 v) {
    unsigned int lo, hi;
    asm("mov.b64 {%0, %1}, %2;" : "=r"(lo), "=r"(hi) : "l"(v));
    return make_float2(__uint_as_float(lo), __uint_as_float(hi));
}

// ---------------- 1. bucket matrix: searchsorted(intervals, d, 'right') = floor(2d)+1
__global__ __launch_bounds__(256) void bucket_kernel(const float* __restrict__ dist) {
    size_t i = ((size_t)blockIdx.x * 256 + threadIdx.x) * 4;
    float4 v = *(const float4*)(dist + i);
    uchar4 o;
    o.x = (unsigned char)min(100, (int)floorf(v.x * 2.0f) + 1);
    o.y = (unsigned char)min(100, (int)floorf(v.y * 2.0f) + 1);
    o.z = (unsigned char)min(100, (int)floorf(v.z * 2.0f) + 1);
    o.w = (unsigned char)min(100, (int)floorf(v.w * 2.0f) + 1);
    *(uchar4*)(g_bk + i) = o;
}

// ---------------- 2. per-row bucket histogram (sample independent) --------------
__global__ __launch_bounds__(256) void hist_kernel() {
    __shared__ int sh[NINT];
    int i = blockIdx.x, t = threadIdx.x;
    if (t < NINT) sh[t] = 0;
    __syncthreads();
    const unsigned char* row = g_bk + (size_t)i * NPOI;
    union { uint4 v; unsigned char b[16]; } bv;
    bv.v = *(const uint4*)(row + t * 16);   // 256 threads * 16B = 4096
    #pragma unroll
    for (int m = 0; m < 16; m++) atomicAdd(&sh[bv.b[m]], 1);
    __syncthreads();
    if (t < NINT) g_histT[t * NPOI + i] = sh[t];
    if (t == 0) g_diag[i] = row[i];
}

// ---------------- 3. per-sample setup: stable sort, gather rows, span LUT -------
__global__ __launch_bounds__(256) void setup_kernel(const float* __restrict__ dist,
                                                    const int* __restrict__ seq,
                                                    const int* __restrict__ ids) {
    __shared__ int sord[NDROWS];
    __shared__ int scnt[NB][NINT];
    int t = threadIdx.x;
    if (t < NDROWS) {                       // stable counting argsort of 32 ids
        int my = ids[t], pos = 0;
        for (int q = 0; q < NDROWS; q++) {
            int v = ids[q];
            if (v < my || (v == my && q < t)) pos++;
        }
        sord[pos] = t;
    }
    for (int e = t; e < NB * NINT; e += 256) (&scnt[0][0])[e] = 0;
    __syncthreads();
    if (t < NDROWS) g_order[t] = sord[t];
    for (int e = t; e < NB * NPOS; e += 256) {
        int s = e >> 8, pos = e & 255, day = pos >> 6, l = pos & 63;
        g_rows[e] = seq[sord[s * DAYS + day] * LL + l] - 1;
    }
    // spans of the LAST day; searchsorted 'left' == ceil(2s) exactly
    for (int e = t; e < NB * (LL - 1); e += 256) {
        int s = e / (LL - 1), tt = e % (LL - 1);
        int lrow = sord[s * DAYS + (DAYS - 1)];
        int a = seq[lrow * LL + tt] - 1;
        int b = seq[lrow * LL + tt + 1] - 1;
        float dv = dist[(size_t)a * NPOI + b];
        int idx = (int)ceilf(dv * 2.0f);
        idx = idx < 0 ? 0 : (idx > 100 ? 100 : idx);
        atomicAdd(&scnt[s][idx], 1);
    }
    __syncthreads();
    for (int e = t; e < NB * NINT; e += 256)
        g_lut[e] = (float)(&scnt[0][0])[e] / 63.0f;
}

// ---------------- 4. degrees from histograms ------------------------------------
__global__ __launch_bounds__(256) void deg_kernel() {
    __shared__ float lc[NINT];
    int s = blockIdx.y, t = threadIdx.x;
    if (t < NINT) lc[t] = g_lut[s * NINT + t];
    __syncthreads();
    int i = blockIdx.x * 256 + t;
    float sum = 1.0f - lc[g_diag[i]];      // diagonal of W forced to 1
    #pragma unroll 101
    for (int k = 0; k < NINT; k++) sum += lc[k] * (float)g_histT[k * NPOI + i];
    g_invdeg[s * NPOI + i] = 1.0f / sqrtf(fmaxf(sum, 1e-24f));
}

// ---------------- 5. Y0 = poi_emb / deg -----------------------------------------
__global__ __launch_bounds__(256) void y0_kernel(const float* __restrict__ poi) {
    int e = blockIdx.x * 256 + threadIdx.x;  // NB*NPOI*DD = 2,097,152
    int d = e & 63, j = (e >> 6) & (NPOI - 1), s = e >> 18;
    g_Y0[e] = poi[(size_t)(j + 1) * DD + d] * g_invdeg[s * NPOI + j];
}

// ---------------- 6. layer-1 GEMM (full 4096 rows) + tanh + Y1 fuse -------------
// C[i][d] = sum_j lut[bk[i][j]] * Y0[j][d]; L1 = tanh(invdeg_i*(C + (1-lut_ii)*Y0[i]))
__global__ __launch_bounds__(256) void gemm1_kernel() {
    __shared__ float Asm[64][64];   // k-major: Asm[k][i]
    __shared__ float Ysm[64][64];   // Ysm[k][d]
    __shared__ float slut[NINT + 3];
    int s = blockIdx.y;
    int rowbase = blockIdx.x * 64;
    int t = threadIdx.x;
    int tx = t & 15, ty = t >> 4;
    if (t < NINT) slut[t] = g_lut[s * NINT + t];
    const float* Yg = g_Y0 + (size_t)s * NPOI * DD;
    const unsigned char* bkp = g_bk + (size_t)(rowbase + (t >> 2)) * NPOI + (t & 3) * 16;
    __syncthreads();

    u64 acc[4][2];
    #pragma unroll
    for (int r = 0; r < 4; r++) { acc[r][0] = 0ULL; acc[r][1] = 0ULL; }

    for (int kb = 0; kb < NPOI; kb += 64) {
        union { uint4 v; unsigned char b[16]; } bv;
        bv.v = *(const uint4*)(bkp + kb);
        int kq = (t & 3) * 16, ia = t >> 2;
        #pragma unroll
        for (int m = 0; m < 16; m++) Asm[kq + m][ia] = slut[bv.b[m]];
        #pragma unroll
        for (int m = 0; m < 4; m++) {
            int idx = t + m * 256;
            int k2 = idx >> 4, d4 = (idx & 15) * 4;
            *(float4*)&Ysm[k2][d4] = *(const float4*)(Yg + (size_t)(kb + k2) * DD + d4);
        }
        __syncthreads();
        #pragma unroll 16
        for (int k = 0; k < 64; k++) {
            float4 af = *(const float4*)&Asm[k][ty * 4];
            union { float4 f; u64 l[2]; } yf;
            yf.f = *(const float4*)&Ysm[k][tx * 4];
            u64 a0 = pack2(af.x), a1 = pack2(af.y), a2 = pack2(af.z), a3 = pack2(af.w);
            acc[0][0] = ffma2(a0, yf.l[0], acc[0][0]); acc[0][1] = ffma2(a0, yf.l[1], acc[0][1]);
            acc[1][0] = ffma2(a1, yf.l[0], acc[1][0]); acc[1][1] = ffma2(a1, yf.l[1], acc[1][1]);
            acc[2][0] = ffma2(a2, yf.l[0], acc[2][0]); acc[2][1] = ffma2(a2, yf.l[1], acc[2][1]);
            acc[3][0] = ffma2(a3, yf.l[0], acc[3][0]); acc[3][1] = ffma2(a3, yf.l[1], acc[3][1]);
        }
        __syncthreads();
    }
    #pragma unroll
    for (int r = 0; r < 4; r++) {
        int i = rowbase + ty * 4 + r;
        float idg = g_invdeg[s * NPOI + i];
        float dterm = 1.0f - slut[g_diag[i]];
        float2 p0 = unpack2(acc[r][0]), p1 = unpack2(acc[r][1]);
        float vals[4] = { p0.x, p0.y, p1.x, p1.y };
        #pragma unroll
        for (int c = 0; c < 4; c++) {
            int d = tx * 4 + c;
            size_t off = ((size_t)s * NPOI + i) * DD + d;
            float l1 = tanhf(idg * (vals[c] + dterm * Yg[(size_t)i * DD + d]));
            g_L1[off] = l1;
            g_Y1[off] = l1 * idg;
        }
    }
}

// ---------------- 7. layer-2 GEMM: only gathered rows, K-split ------------------
__global__ __launch_bounds__(256) void gemm2_kernel() {
    __shared__ float Asm[64][32];
    __shared__ float Ysm[64][64];
    __shared__ float slut[NINT + 3];
    __shared__ int srows[32];
    int pb = blockIdx.x;       // 0..7 (32 positions each)
    int s  = blockIdx.y;
    int kc = blockIdx.z;       // 0..KC-1
    int t  = threadIdx.x;
    int tx = t & 15, ty = t >> 4;
    if (t < NINT) slut[t] = g_lut[s * NINT + t];
    if (t < 32)  srows[t] = g_rows[s * NPOS + pb * 32 + t];
    __syncthreads();
    const float* Yg = g_Y1 + (size_t)s * NPOI * DD;
    float acc[2][4] = {};
    int ra = t >> 3;               // 0..31
    int kq = (t & 7) * 8;
    const unsigned char* bkp = g_bk + (size_t)srows[ra] * NPOI + kq;
    int k0 = kc * (NPOI / KC), k1 = k0 + (NPOI / KC);
    for (int kb = k0; kb < k1; kb += 64) {
        union { uint2 v; unsigned char b[8]; } bv;
        bv.v = *(const uint2*)(bkp + kb);
        #pragma unroll
        for (int m = 0; m < 8; m++) Asm[kq + m][ra] = slut[bv.b[m]];
        #pragma unroll
        for (int m = 0; m < 4; m++) {
            int idx = t + m * 256;
            int k2 = idx >> 4, d4 = (idx & 15) * 4;
            *(float4*)&Ysm[k2][d4] = *(const float4*)(Yg + (size_t)(kb + k2) * DD + d4);
        }
        __syncthreads();
        #pragma unroll 16
        for (int k = 0; k < 64; k++) {
            float a0 = Asm[k][ty * 2], a1 = Asm[k][ty * 2 + 1];
            float4 y = *(const float4*)&Ysm[k][tx * 4];
            acc[0][0] += a0 * y.x; acc[0][1] += a0 * y.y;
            acc[0][2] += a0 * y.z; acc[0][3] += a0 * y.w;
            acc[1][0] += a1 * y.x; acc[1][1] += a1 * y.y;
            acc[1][2] += a1 * y.z; acc[1][3] += a1 * y.w;
        }
        __syncthreads();
    }
    #pragma unroll
    for (int r = 0; r < 2; r++) {
        int pos = pb * 32 + ty * 2 + r;
        #pragma unroll
        for (int c = 0; c < 4; c++)
            g_part[(((size_t)kc * NB + s) * NPOS + pos) * DD + tx * 4 + c] = acc[r][c];
    }
}

// ---------------- 8. finalize: sum K-splits, tanh, out = 8*(poi+L1+L2) ----------
__global__ __launch_bounds__(256) void finalize_kernel(const float* __restrict__ poi,
                                                       float* __restrict__ out) {
    int e = blockIdx.x * 256 + threadIdx.x;   // NB*NPOS*DD = 131072
    int d = e & 63;
    int pl = e >> 6;
    int pos = pl & 255;
    int s = pl >> 8;
    int r = g_rows[s * NPOS + pos];
    float acc = 0.0f;
    #pragma unroll
    for (int kc = 0; kc < KC; kc++)
        acc += g_part[(((size_t)kc * NB + s) * NPOS + pos) * DD + d];
    float idg = g_invdeg[s * NPOI + r];
    float dterm = 1.0f - g_lut[s * NINT + g_diag[r]];
    size_t off = ((size_t)s * NPOI + r) * DD + d;
    float l2 = tanhf(idg * (acc + dterm * g_Y1[off]));
    float v = 8.0f * (poi[(size_t)(r + 1) * DD + d] + g_L1[off] + l2);
    int day = pos >> 6, l = pos & 63;
    out[(((size_t)(s * DAYS + day)) * LL + l) * DD + d] = v;
}

// ---------------- launch ---------------------------------------------------------
extern "C" void kernel_launch(void* const* d_in, const int* in_sizes, int n_in,
                              void* d_out, int out_size) {
    (void)in_sizes; (void)n_in; (void)out_size;
    const float* poi  = (const float*)d_in[0];   // (4097, 64)
    const float* dist = (const float*)d_in[1];   // (4096, 4096)
    const int*   seq  = (const int*)d_in[2];     // (32, 64)
    const int*   ids  = (const int*)d_in[3];     // (32,)
    float* out = (float*)d_out;                  // (32, 64, 64)

    bucket_kernel  <<<(NPOI * NPOI) / 1024, 256>>>(dist);
    hist_kernel    <<<NPOI, 256>>>();
    setup_kernel   <<<1, 256>>>(dist, seq, ids);
    deg_kernel     <<<dim3(NPOI / 256, NB), 256>>>();
    y0_kernel      <<<(NB * NPOI * DD) / 256, 256>>>(poi);
    gemm1_kernel   <<<dim3(NPOI / 64, NB), 256>>>();
    gemm2_kernel   <<<dim3(NPOS / 32, NB, KC), 256>>>();
    finalize_kernel<<<(NB * NPOS * DD) / 256, 256>>>(poi, out);
}

// round 2
// speedup vs baseline: 1.0006x; 1.0006x over previous
#include <cuda_runtime.h>
#include <cstdint>
#include <cstddef>

#define NPOI 4096
#define DD   64
#define NB   8
#define DAYS 4
#define LL   64
#define NDROWS (NB*DAYS)   // 32
#define NPOS   (DAYS*LL)   // 256 gathered positions per sample
#define NINT   101
#define KC     4           // K-chunks for layer-2 GEMM

typedef unsigned long long u64;

// ---------------- scratch (device globals: allocation-free per harness rules) ----
__device__ __align__(16) unsigned char g_bk[(size_t)NPOI * NPOI];   // 16 MB bucket matrix
__device__ unsigned char g_diag[NPOI];
__device__ int   g_histT[NINT * NPOI];       // transposed row-bucket histogram
__device__ float g_lut[NB * NINT];           // per-sample LUT: cnt[k]/63
__device__ float g_invdeg[NB * NPOI];
__device__ int   g_order[NDROWS];
__device__ int   g_rows[NB * NPOS];          // gathered poi row indices (0-based)
__device__ float g_Y0[(size_t)NB * NPOI * DD];  // poi_emb / deg
__device__ float g_L1[(size_t)NB * NPOI * DD];  // layer-1 (tanh)
__device__ float g_Y1[(size_t)NB * NPOI * DD];  // layer1 / deg
__device__ float g_part[(size_t)KC * NB * NPOS * DD]; // layer-2 K-split partials

// ---------------- packed fp32x2 helpers (FFMA2 only reachable via PTX) ----------
__device__ __forceinline__ u64 pack2(float v) {
    u64 r; unsigned int u = __float_as_uint(v);
    asm("mov.b64 %0, {%1, %1};" : "=l"(r) : "r"(u));
    return r;
}
__device__ __forceinline__ u64 ffma2(u64 a, u64 b, u64 c) {
    u64 d; asm("fma.rn.f32x2 %0, %1, %2, %3;" : "=l"(d) : "l"(a), "l"(b), "l"(c));
    return d;
}
__device__ __forceinline__ float2 unpack2(u64 v) {
    unsigned int lo, hi;
    asm("mov.b64 {%0, %1}, %2;" : "=r"(lo), "=r"(hi) : "l"(v));
    return make_float2(__uint_as_float(lo), __uint_as_float(hi));
}

// ---------------- 1. bucket matrix: searchsorted(intervals, d, 'right') = floor(2d)+1
__global__ __launch_bounds__(256) void bucket_kernel(const float* __restrict__ dist) {
    size_t i = ((size_t)blockIdx.x * 256 + threadIdx.x) * 4;
    float4 v = *(const float4*)(dist + i);
    uchar4 o;
    o.x = (unsigned char)min(100, (int)floorf(v.x * 2.0f) + 1);
    o.y = (unsigned char)min(100, (int)floorf(v.y * 2.0f) + 1);
    o.z = (unsigned char)min(100, (int)floorf(v.z * 2.0f) + 1);
    o.w = (unsigned char)min(100, (int)floorf(v.w * 2.0f) + 1);
    *(uchar4*)(g_bk + i) = o;
}

// ---------------- 2. per-row bucket histogram (sample independent) --------------
__global__ __launch_bounds__(256) void hist_kernel() {
    __shared__ int sh[NINT];
    int i = blockIdx.x, t = threadIdx.x;
    if (t < NINT) sh[t] = 0;
    __syncthreads();
    const unsigned char* row = g_bk + (size_t)i * NPOI;
    union { uint4 v; unsigned char b[16]; } bv;
    bv.v = *(const uint4*)(row + t * 16);   // 256 threads * 16B = 4096
    #pragma unroll
    for (int m = 0; m < 16; m++) atomicAdd(&sh[bv.b[m]], 1);
    __syncthreads();
    if (t < NINT) g_histT[t * NPOI + i] = sh[t];
    if (t == 0) g_diag[i] = row[i];
}

// ---------------- 3. per-sample setup: stable sort, gather rows, span LUT -------
__global__ __launch_bounds__(256) void setup_kernel(const float* __restrict__ dist,
                                                    const int* __restrict__ seq,
                                                    const int* __restrict__ ids) {
    __shared__ int sord[NDROWS];
    __shared__ int scnt[NB][NINT];
    int t = threadIdx.x;
    if (t < NDROWS) {                       // stable counting argsort of 32 ids
        int my = ids[t], pos = 0;
        for (int q = 0; q < NDROWS; q++) {
            int v = ids[q];
            if (v < my || (v == my && q < t)) pos++;
        }
        sord[pos] = t;
    }
    for (int e = t; e < NB * NINT; e += 256) (&scnt[0][0])[e] = 0;
    __syncthreads();
    if (t < NDROWS) g_order[t] = sord[t];
    for (int e = t; e < NB * NPOS; e += 256) {
        int s = e >> 8, pos = e & 255, day = pos >> 6, l = pos & 63;
        g_rows[e] = seq[sord[s * DAYS + day] * LL + l] - 1;
    }
    // spans of the LAST day; searchsorted 'left' == ceil(2s) exactly
    for (int e = t; e < NB * (LL - 1); e += 256) {
        int s = e / (LL - 1), tt = e % (LL - 1);
        int lrow = sord[s * DAYS + (DAYS - 1)];
        int a = seq[lrow * LL + tt] - 1;
        int b = seq[lrow * LL + tt + 1] - 1;
        float dv = dist[(size_t)a * NPOI + b];
        int idx = (int)ceilf(dv * 2.0f);
        idx = idx < 0 ? 0 : (idx > 100 ? 100 : idx);
        atomicAdd(&scnt[s][idx], 1);
    }
    __syncthreads();
    for (int e = t; e < NB * NINT; e += 256)
        g_lut[e] = (float)(&scnt[0][0])[e] / 63.0f;
}

// ---------------- 4. degrees from histograms ------------------------------------
__global__ __launch_bounds__(256) void deg_kernel() {
    __shared__ float lc[NINT];
    int s = blockIdx.y, t = threadIdx.x;
    if (t < NINT) lc[t] = g_lut[s * NINT + t];
    __syncthreads();
    int i = blockIdx.x * 256 + t;
    float sum = 1.0f - lc[g_diag[i]];      // diagonal of W forced to 1
    #pragma unroll 101
    for (int k = 0; k < NINT; k++) sum += lc[k] * (float)g_histT[k * NPOI + i];
    g_invdeg[s * NPOI + i] = 1.0f / sqrtf(fmaxf(sum, 1e-24f));
}

// ---------------- 5. Y0 = poi_emb / deg -----------------------------------------
__global__ __launch_bounds__(256) void y0_kernel(const float* __restrict__ poi) {
    int e = blockIdx.x * 256 + threadIdx.x;  // NB*NPOI*DD = 2,097,152
    int d = e & 63, j = (e >> 6) & (NPOI - 1), s = e >> 18;
    g_Y0[e] = poi[(size_t)(j + 1) * DD + d] * g_invdeg[s * NPOI + j];
}

// ---------------- 6. layer-1 GEMM (full 4096 rows) + tanh + Y1 fuse -------------
// C[i][d] = sum_j lut[bk[i][j]] * Y0[j][d]; L1 = tanh(invdeg_i*(C + (1-lut_ii)*Y0[i]))
__global__ __launch_bounds__(256) void gemm1_kernel() {
    __shared__ float Asm[64][64];   // k-major: Asm[k][i]
    __shared__ float Ysm[64][64];   // Ysm[k][d]
    __shared__ float slut[NINT + 3];
    int s = blockIdx.y;
    int rowbase = blockIdx.x * 64;
    int t = threadIdx.x;
    int tx = t & 15, ty = t >> 4;
    if (t < NINT) slut[t] = g_lut[s * NINT + t];
    const float* Yg = g_Y0 + (size_t)s * NPOI * DD;
    const unsigned char* bkp = g_bk + (size_t)(rowbase + (t >> 2)) * NPOI + (t & 3) * 16;
    __syncthreads();

    u64 acc[4][2];
    #pragma unroll
    for (int r = 0; r < 4; r++) { acc[r][0] = 0ULL; acc[r][1] = 0ULL; }

    for (int kb = 0; kb < NPOI; kb += 64) {
        union { uint4 v; unsigned char b[16]; } bv;
        bv.v = *(const uint4*)(bkp + kb);
        int kq = (t & 3) * 16, ia = t >> 2;
        #pragma unroll
        for (int m = 0; m < 16; m++) Asm[kq + m][ia] = slut[bv.b[m]];
        #pragma unroll
        for (int m = 0; m < 4; m++) {
            int idx = t + m * 256;
            int k2 = idx >> 4, d4 = (idx & 15) * 4;
            *(float4*)&Ysm[k2][d4] = *(const float4*)(Yg + (size_t)(kb + k2) * DD + d4);
        }
        __syncthreads();
        #pragma unroll 16
        for (int k = 0; k < 64; k++) {
            float4 af = *(const float4*)&Asm[k][ty * 4];
            union { float4 f; u64 l[2]; } yf;
            yf.f = *(const float4*)&Ysm[k][tx * 4];
            u64 a0 = pack2(af.x), a1 = pack2(af.y), a2 = pack2(af.z), a3 = pack2(af.w);
            acc[0][0] = ffma2(a0, yf.l[0], acc[0][0]); acc[0][1] = ffma2(a0, yf.l[1], acc[0][1]);
            acc[1][0] = ffma2(a1, yf.l[0], acc[1][0]); acc[1][1] = ffma2(a1, yf.l[1], acc[1][1]);
            acc[2][0] = ffma2(a2, yf.l[0], acc[2][0]); acc[2][1] = ffma2(a2, yf.l[1], acc[2][1]);
            acc[3][0] = ffma2(a3, yf.l[0], acc[3][0]); acc[3][1] = ffma2(a3, yf.l[1], acc[3][1]);
        }
        __syncthreads();
    }
    #pragma unroll
    for (int r = 0; r < 4; r++) {
        int i = rowbase + ty * 4 + r;
        float idg = g_invdeg[s * NPOI + i];
        float dterm = 1.0f - slut[g_diag[i]];
        float2 p0 = unpack2(acc[r][0]), p1 = unpack2(acc[r][1]);
        float vals[4] = { p0.x, p0.y, p1.x, p1.y };
        #pragma unroll
        for (int c = 0; c < 4; c++) {
            int d = tx * 4 + c;
            size_t off = ((size_t)s * NPOI + i) * DD + d;
            float l1 = tanhf(idg * (vals[c] + dterm * Yg[(size_t)i * DD + d]));
            g_L1[off] = l1;
            g_Y1[off] = l1 * idg;
        }
    }
}

// ---------------- 7. layer-2 GEMM: only gathered rows, K-split ------------------
__global__ __launch_bounds__(256) void gemm2_kernel() {
    __shared__ float Asm[64][32];
    __shared__ float Ysm[64][64];
    __shared__ float slut[NINT + 3];
    __shared__ int srows[32];
    int pb = blockIdx.x;       // 0..7 (32 positions each)
    int s  = blockIdx.y;
    int kc = blockIdx.z;       // 0..KC-1
    int t  = threadIdx.x;
    int tx = t & 15, ty = t >> 4;
    if (t < NINT) slut[t] = g_lut[s * NINT + t];
    if (t < 32)  srows[t] = g_rows[s * NPOS + pb * 32 + t];
    __syncthreads();
    const float* Yg = g_Y1 + (size_t)s * NPOI * DD;
    float acc[2][4] = {};
    int ra = t >> 3;               // 0..31
    int kq = (t & 7) * 8;
    const unsigned char* bkp = g_bk + (size_t)srows[ra] * NPOI + kq;
    int k0 = kc * (NPOI / KC), k1 = k0 + (NPOI / KC);
    for (int kb = k0; kb < k1; kb += 64) {
        union { uint2 v; unsigned char b[8]; } bv;
        bv.v = *(const uint2*)(bkp + kb);
        #pragma unroll
        for (int m = 0; m < 8; m++) Asm[kq + m][ra] = slut[bv.b[m]];
        #pragma unroll
        for (int m = 0; m < 4; m++) {
            int idx = t + m * 256;
            int k2 = idx >> 4, d4 = (idx & 15) * 4;
            *(float4*)&Ysm[k2][d4] = *(const float4*)(Yg + (size_t)(kb + k2) * DD + d4);
        }
        __syncthreads();
        #pragma unroll 16
        for (int k = 0; k < 64; k++) {
            float a0 = Asm[k][ty * 2], a1 = Asm[k][ty * 2 + 1];
            float4 y = *(const float4*)&Ysm[k][tx * 4];
            acc[0][0] += a0 * y.x; acc[0][1] += a0 * y.y;
            acc[0][2] += a0 * y.z; acc[0][3] += a0 * y.w;
            acc[1][0] += a1 * y.x; acc[1][1] += a1 * y.y;
            acc[1][2] += a1 * y.z; acc[1][3] += a1 * y.w;
        }
        __syncthreads();
    }
    #pragma unroll
    for (int r = 0; r < 2; r++) {
        int pos = pb * 32 + ty * 2 + r;
        #pragma unroll
        for (int c = 0; c < 4; c++)
            g_part[(((size_t)kc * NB + s) * NPOS + pos) * DD + tx * 4 + c] = acc[r][c];
    }
}

// ---------------- 8. finalize: sum K-splits, tanh, out = 8*(poi+L1+L2) ----------
__global__ __launch_bounds__(256) void finalize_kernel(const float* __restrict__ poi,
                                                       float* __restrict__ out) {
    int e = blockIdx.x * 256 + threadIdx.x;   // NB*NPOS*DD = 131072
    int d = e & 63;
    int pl = e >> 6;
    int pos = pl & 255;
    int s = pl >> 8;
    int r = g_rows[s * NPOS + pos];
    float acc = 0.0f;
    #pragma unroll
    for (int kc = 0; kc < KC; kc++)
        acc += g_part[(((size_t)kc * NB + s) * NPOS + pos) * DD + d];
    float idg = g_invdeg[s * NPOI + r];
    float dterm = 1.0f - g_lut[s * NINT + g_diag[r]];
    size_t off = ((size_t)s * NPOI + r) * DD + d;
    float l2 = tanhf(idg * (acc + dterm * g_Y1[off]));
    float v = 8.0f * (poi[(size_t)(r + 1) * DD + d] + g_L1[off] + l2);
    int day = pos >> 6, l = pos & 63;
    out[(((size_t)(s * DAYS + day)) * LL + l) * DD + d] = v;
}

// ---------------- launch ---------------------------------------------------------
extern "C" void kernel_launch(void* const* d_in, const int* in_sizes, int n_in,
                              void* d_out, int out_size) {
    (void)in_sizes; (void)n_in; (void)out_size;
    const float* poi  = (const float*)d_in[0];   // (4097, 64)
    const float* dist = (const float*)d_in[1];   // (4096, 4096)
    const int*   seq  = (const int*)d_in[2];     // (32, 64)
    const int*   ids  = (const int*)d_in[3];     // (32,)
    float* out = (float*)d_out;                  // (32, 64, 64)

    bucket_kernel  <<<(NPOI * NPOI) / 1024, 256>>>(dist);
    hist_kernel    <<<NPOI, 256>>>();
    setup_kernel   <<<1, 256>>>(dist, seq, ids);
    deg_kernel     <<<dim3(NPOI / 256, NB), 256>>>();
    y0_kernel      <<<(NB * NPOI * DD) / 256, 256>>>(poi);
    gemm1_kernel   <<<dim3(NPOI / 64, NB), 256>>>();
    gemm2_kernel   <<<dim3(NPOS / 32, NB, KC), 256>>>();
    finalize_kernel<<<(NB * NPOS * DD) / 256, 256>>>(poi, out);
}

// round 4
// speedup vs baseline: 2.0821x; 2.0809x over previous
#include <cuda_runtime.h>
#include <cuda_bf16.h>
#include <cstdint>
#include <cstddef>

#define NPOI 4096
#define DD   64
#define NB   8
#define DAYS 4
#define LL   64
#define NDROWS 32
#define NPOS   256
#define NINT 101
#define KC   4
#define MT   128
#define KT   64
#define NC   (NPOI/KT)
#define SMEM_TOT (1024 + 32768)

typedef unsigned long long u64;
typedef unsigned int u32;

__device__ __align__(16) unsigned char g_bk[(size_t)NPOI * NPOI];
__device__ unsigned char g_diag[NPOI];
__device__ int   g_histT[NINT * NPOI];
__device__ float g_lut[NB * NINT];
__device__ float g_cntf[NB * NINT];
__device__ float g_invdeg[NB * NPOI];
__device__ int   g_rows[NB * NPOS];
__device__ float g_Y0[(size_t)NB * NPOI * DD];
__device__ float g_L1[(size_t)NB * NPOI * DD];
__device__ float g_Y1[(size_t)NB * NPOI * DD];
__device__ __align__(16) __nv_bfloat16 g_Yth[(size_t)NB * DD * NPOI];
__device__ __align__(16) __nv_bfloat16 g_Ytl[(size_t)NB * DD * NPOI];
__device__ float g_part[(size_t)KC * NB * NPOS * DD];

__device__ __forceinline__ u32 smem_u32(const void* p) {
    u32 a; asm("{ .reg .u64 t; cvta.to.shared.u64 t, %1; cvt.u32.u64 %0, t; }" : "=r"(a) : "l"(p));
    return a;
}
__device__ __forceinline__ u32 swz(u32 o) { return o ^ ((o >> 3) & 0x70); }
__device__ __forceinline__ void ldsm4(u32& r0, u32& r1, u32& r2, u32& r3, u32 a) {
    asm volatile("ldmatrix.sync.aligned.m8n8.x4.shared.b16 {%0,%1,%2,%3}, [%4];"
        : "=r"(r0), "=r"(r1), "=r"(r2), "=r"(r3) : "r"(a));
}
__device__ __forceinline__ void mma16816(float* c, const u32* a, u32 b0, u32 b1) {
    asm volatile("mma.sync.aligned.m16n8k16.row.col.f32.bf16.bf16.f32 "
        "{%0,%1,%2,%3}, {%4,%5,%6,%7}, {%8,%9}, {%0,%1,%2,%3};"
        : "+f"(c[0]), "+f"(c[1]), "+f"(c[2]), "+f"(c[3])
        : "r"(a[0]), "r"(a[1]), "r"(a[2]), "r"(a[3]), "r"(b0), "r"(b1));
}

__global__ __launch_bounds__(256) void bucket_kernel(const float* __restrict__ dist) {
    size_t i = ((size_t)blockIdx.x * 256 + threadIdx.x) * 4;
    float4 v = *(const float4*)(dist + i);
    uchar4 o;
    o.x = (unsigned char)min(100, (int)floorf(v.x * 2.0f) + 1);
    o.y = (unsigned char)min(100, (int)floorf(v.y * 2.0f) + 1);
    o.z = (unsigned char)min(100, (int)floorf(v.z * 2.0f) + 1);
    o.w = (unsigned char)min(100, (int)floorf(v.w * 2.0f) + 1);
    *(uchar4*)(g_bk + i) = o;
}

__global__ __launch_bounds__(256) void hist_kernel() {
    __shared__ int sh[NINT];
    int i = blockIdx.x, t = threadIdx.x;
    if (t < NINT) sh[t] = 0;
    __syncthreads();
    const unsigned char* row = g_bk + (size_t)i * NPOI;
    union { uint4 v; unsigned char b[16]; } bv;
    bv.v = *(const uint4*)(row + t * 16);
    #pragma unroll
    for (int m = 0; m < 16; m++) atomicAdd(&sh[bv.b[m]], 1);
    __syncthreads();
    if (t < NINT) g_histT[t * NPOI + i] = sh[t];
    if (t == 0) g_diag[i] = row[i];
}

__global__ __launch_bounds__(256) void setup_kernel(const float* __restrict__ dist,
                                                    const int* __restrict__ seq,
                                                    const int* __restrict__ ids) {
    __shared__ int sord[NDROWS];
    __shared__ int scnt[NB][NINT];
    int t = threadIdx.x;
    if (t < NDROWS) {
        int my = ids[t], pos = 0;
        for (int q = 0; q < NDROWS; q++) {
            int v = ids[q];
            if (v < my || (v == my && q < t)) pos++;
        }
        sord[pos] = t;
    }
    for (int e = t; e < NB * NINT; e += 256) (&scnt[0][0])[e] = 0;
    __syncthreads();
    for (int e = t; e < NB * NPOS; e += 256) {
        int s = e >> 8, pos = e & 255, day = pos >> 6, l = pos & 63;
        g_rows[e] = seq[sord[s * DAYS + day] * LL + l] - 1;
    }
    for (int e = t; e < NB * (LL - 1); e += 256) {
        int s = e / (LL - 1), tt = e % (LL - 1);
        int lrow = sord[s * DAYS + (DAYS - 1)];
        int a = seq[lrow * LL + tt] - 1;
        int b = seq[lrow * LL + tt + 1] - 1;
        float dv = dist[(size_t)a * NPOI + b];
        int idx = (int)ceilf(dv * 2.0f);
        idx = idx < 0 ? 0 : (idx > 100 ? 100 : idx);
        atomicAdd(&scnt[s][idx], 1);
    }
    __syncthreads();
    for (int e = t; e < NB * NINT; e += 256) {
        int cv = (&scnt[0][0])[e];
        g_lut[e]  = (float)cv / 63.0f;
        g_cntf[e] = (float)cv;
    }
}

__global__ __launch_bounds__(256) void deg_kernel() {
    __shared__ float lc[NINT];
    int s = blockIdx.y, t = threadIdx.x;
    if (t < NINT) lc[t] = g_lut[s * NINT + t];
    __syncthreads();
    int i = blockIdx.x * 256 + t;
    float sum = 1.0f - lc[g_diag[i]];
    #pragma unroll 101
    for (int k = 0; k < NINT; k++) sum += lc[k] * (float)g_histT[k * NPOI + i];
    g_invdeg[s * NPOI + i] = 1.0f / sqrtf(fmaxf(sum, 1e-24f));
}

__global__ __launch_bounds__(256) void y0t_kernel(const float* __restrict__ poi) {
    __shared__ float ts[64][65];
    int s = blockIdx.y, jbase = blockIdx.x * 64, t = threadIdx.x;
    #pragma unroll
    for (int r = 0; r < 16; r++) {
        int idx = r * 256 + t;
        int jl = idx >> 6, d = idx & 63;
        int j = jbase + jl;
        float y = poi[(size_t)(j + 1) * DD + d] * g_invdeg[s * NPOI + j];
        g_Y0[((size_t)s * NPOI + j) * DD + d] = y;
        ts[jl][d] = y;
    }
    __syncthreads();
    #pragma unroll
    for (int r = 0; r < 16; r++) {
        int idx = r * 256 + t;
        int d = idx >> 6, jl = idx & 63;
        float y = ts[jl][d];
        __nv_bfloat16 hb = __float2bfloat16(y);
        __nv_bfloat16 lb = __float2bfloat16(y - __bfloat162float(hb));
        size_t off = ((size_t)s * DD + d) * NPOI + jbase + jl;
        g_Yth[off] = hb;
        g_Ytl[off] = lb;
    }
}

// layer-1: C[128x64] = CNT @ (Yhi + Ylo) via mma.sync bf16, fp32 accum.
extern __shared__ __align__(1024) char dsm[];
__global__ __launch_bounds__(256) void gemm1_mma_kernel() {
    const int t = threadIdx.x, wid = t >> 5, lane = t & 31;
    const int s = blockIdx.y;
    const int rowbase = blockIdx.x * MT;
    unsigned short* slut = (unsigned short*)dsm;       // 101 bf16 counts
    char* Ab = dsm + 1024;                             // [128][64] bf16 SW128
    char* Bh = Ab + 16384;                             // [64][64] bf16 SW128
    char* Bl = Bh + 8192;
    const u32 Ab_u = smem_u32(Ab), Bh_u = smem_u32(Bh), Bl_u = smem_u32(Bl);

    if (t < NINT) {
        __nv_bfloat16 b = __float2bfloat16(g_cntf[s * NINT + t]);
        slut[t] = *(unsigned short*)&b;
    }
    __syncthreads();

    // producer mapping
    const int pm = t >> 1, ph = t & 1;                 // A: row, k-half(32)
    const int bt = t >> 7, bd = (t >> 1) & 63, bh = t & 1; // B: hi/lo, d-row, k-half
    const unsigned char* gA = g_bk + (size_t)(rowbase + pm) * NPOI + ph * 32;
    const __nv_bfloat16* gB = (bt == 0 ? g_Yth : g_Ytl)
                              + ((size_t)s * DD + bd) * NPOI + bh * 32;
    char* myB = (bt == 0 ? Bh : Bl);

    // consumer mapping: 4 warps along M(32), 2 along N(32)
    const int wm = wid & 3, wn = wid >> 2;
    float acc[2][4][4];
    #pragma unroll
    for (int a = 0; a < 2; a++)
        #pragma unroll
        for (int b = 0; b < 4; b++)
            #pragma unroll
            for (int c = 0; c < 4; c++) acc[a][b][c] = 0.0f;

    uint4 pa[2], pb[4];
    pa[0] = *(const uint4*)(gA);      pa[1] = *(const uint4*)(gA + 16);
    #pragma unroll
    for (int v = 0; v < 4; v++) pb[v] = *(const uint4*)(gB + v * 8);

    for (int c = 0; c < NC; c++) {
        // --- store staged regs into smem (A through LUT) ---
        #pragma unroll
        for (int u2 = 0; u2 < 2; u2++) {
            union { uint4 v; unsigned char b[16]; } q;
            q.v = pa[u2];
            #pragma unroll
            for (int pp = 0; pp < 8; pp++) {
                u32 pr = (u32)slut[q.b[2 * pp]] | ((u32)slut[q.b[2 * pp + 1]] << 16);
                int kl = ph * 32 + u2 * 16 + pp * 2;
                *(u32*)(Ab + swz((u32)(pm * 128 + kl * 2))) = pr;
            }
        }
        #pragma unroll
        for (int v = 0; v < 4; v++)
            *(uint4*)(myB + swz((u32)(bd * 128 + bh * 64 + v * 16))) = pb[v];
        __syncthreads();
        // --- prefetch next chunk ---
        if (c + 1 < NC) {
            int kb = (c + 1) * KT;
            pa[0] = *(const uint4*)(gA + kb);  pa[1] = *(const uint4*)(gA + kb + 16);
            #pragma unroll
            for (int v = 0; v < 4; v++) pb[v] = *(const uint4*)(gB + kb + v * 8);
        }
        // --- mma over this chunk ---
        #pragma unroll
        for (int ks = 0; ks < 4; ks++) {
            const int k0 = ks * 16;
            u32 afr[2][4];
            #pragma unroll
            for (int mi = 0; mi < 2; mi++) {
                int row = wm * 32 + mi * 16 + (lane & 15);
                u32 ad = Ab_u + swz((u32)(row * 128 + (k0 + (lane >> 4) * 8) * 2));
                ldsm4(afr[mi][0], afr[mi][1], afr[mi][2], afr[mi][3], ad);
            }
            #pragma unroll
            for (int hh = 0; hh < 2; hh++) {
                u32 bbase = hh == 0 ? Bh_u : Bl_u;
                #pragma unroll
                for (int ni2 = 0; ni2 < 2; ni2++) {
                    int nr = wn * 32 + ni2 * 16 + (lane & 15);
                    u32 bd2 = bbase + swz((u32)(nr * 128 + (k0 + (lane >> 4) * 8) * 2));
                    u32 r0, r1, r2, r3;
                    ldsm4(r0, r1, r2, r3, bd2);
                    #pragma unroll
                    for (int mi = 0; mi < 2; mi++) {
                        mma16816(acc[mi][ni2 * 2],     afr[mi], r0, r2);
                        mma16816(acc[mi][ni2 * 2 + 1], afr[mi], r1, r3);
                    }
                }
            }
        }
        __syncthreads();
    }

    // --- epilogue: /63, diag fix, tanh; write L1, Y1 ---
    #pragma unroll
    for (int mi = 0; mi < 2; mi++) {
        #pragma unroll
        for (int e2 = 0; e2 < 2; e2++) {          // row sub (e>>1)
            int i = rowbase + wm * 32 + mi * 16 + (lane >> 2) + e2 * 8;
            float idg = g_invdeg[s * NPOI + i];
            float dterm = 1.0f - g_lut[s * NINT + g_diag[i]];
            const float* y0r = g_Y0 + ((size_t)s * NPOI + i) * DD;
            float* l1r = g_L1 + ((size_t)s * NPOI + i) * DD;
            float* y1r = g_Y1 + ((size_t)s * NPOI + i) * DD;
            #pragma unroll
            for (int ni = 0; ni < 4; ni++) {
                #pragma unroll
                for (int e1 = 0; e1 < 2; e1++) {  // col sub (e&1)
                    int d = wn * 32 + ni * 8 + (lane & 3) * 2 + e1;
                    float cf = acc[mi][ni][e2 * 2 + e1] * (1.0f / 63.0f);
                    float l1 = tanhf(idg * (cf + dterm * y0r[d]));
                    l1r[d] = l1;
                    y1r[d] = l1 * idg;
                }
            }
        }
    }
}

__global__ __launch_bounds__(256) void gemm2_kernel() {
    __shared__ float Asm[64][32];
    __shared__ float Ysm[64][64];
    __shared__ float slut[NINT + 3];
    __shared__ int srows[32];
    int pb = blockIdx.x, s = blockIdx.y, kc = blockIdx.z, t = threadIdx.x;
    int tx = t & 15, ty = t >> 4;
    if (t < NINT) slut[t] = g_lut[s * NINT + t];
    if (t < 32)  srows[t] = g_rows[s * NPOS + pb * 32 + t];
    __syncthreads();
    const float* Yg = g_Y1 + (size_t)s * NPOI * DD;
    float acc[2][4] = {};
    int ra = t >> 3, kq = (t & 7) * 8;
    const unsigned char* bkp = g_bk + (size_t)srows[ra] * NPOI + kq;
    int k0 = kc * (NPOI / KC), k1 = k0 + (NPOI / KC);
    for (int kb = k0; kb < k1; kb += 64) {
        union { uint2 v; unsigned char b[8]; } bv;
        bv.v = *(const uint2*)(bkp + kb);
        #pragma unroll
        for (int m = 0; m < 8; m++) Asm[kq + m][ra] = slut[bv.b[m]];
        #pragma unroll
        for (int m = 0; m < 4; m++) {
            int idx = t + m * 256;
            int k2 = idx >> 4, d4 = (idx & 15) * 4;
            *(float4*)&Ysm[k2][d4] = *(const float4*)(Yg + (size_t)(kb + k2) * DD + d4);
        }
        __syncthreads();
        #pragma unroll 16
        for (int k = 0; k < 64; k++) {
            float a0 = Asm[k][ty * 2], a1 = Asm[k][ty * 2 + 1];
            float4 y = *(const float4*)&Ysm[k][tx * 4];
            acc[0][0] += a0 * y.x; acc[0][1] += a0 * y.y;
            acc[0][2] += a0 * y.z; acc[0][3] += a0 * y.w;
            acc[1][0] += a1 * y.x; acc[1][1] += a1 * y.y;
            acc[1][2] += a1 * y.z; acc[1][3] += a1 * y.w;
        }
        __syncthreads();
    }
    #pragma unroll
    for (int r = 0; r < 2; r++) {
        int pos = pb * 32 + ty * 2 + r;
        #pragma unroll
        for (int c = 0; c < 4; c++)
            g_part[(((size_t)kc * NB + s) * NPOS + pos) * DD + tx * 4 + c] = acc[r][c];
    }
}

__global__ __launch_bounds__(256) void finalize_kernel(const float* __restrict__ poi,
                                                       float* __restrict__ out) {
    int e = blockIdx.x * 256 + threadIdx.x;
    int d = e & 63, pl = e >> 6, pos = pl & 255, s = pl >> 8;
    int r = g_rows[s * NPOS + pos];
    float acc = 0.0f;
    #pragma unroll
    for (int kc = 0; kc < KC; kc++)
        acc += g_part[(((size_t)kc * NB + s) * NPOS + pos) * DD + d];
    float idg = g_invdeg[s * NPOI + r];
    float dterm = 1.0f - g_lut[s * NINT + g_diag[r]];
    size_t off = ((size_t)s * NPOI + r) * DD + d;
    float l2 = tanhf(idg * (acc + dterm * g_Y1[off]));
    float v = 8.0f * (poi[(size_t)(r + 1) * DD + d] + g_L1[off] + l2);
    int day = pos >> 6, l = pos & 63;
    out[(((size_t)(s * DAYS + day)) * LL + l) * DD + d] = v;
}

extern "C" void kernel_launch(void* const* d_in, const int* in_sizes, int n_in,
                              void* d_out, int out_size) {
    (void)in_sizes; (void)n_in; (void)out_size;
    const float* poi  = (const float*)d_in[0];
    const float* dist = (const float*)d_in[1];
    const int*   seq  = (const int*)d_in[2];
    const int*   ids  = (const int*)d_in[3];
    float* out = (float*)d_out;

    cudaFuncSetAttribute(gemm1_mma_kernel, cudaFuncAttributeMaxDynamicSharedMemorySize, SMEM_TOT);

    bucket_kernel  <<<(NPOI * NPOI) / 1024, 256>>>(dist);
    hist_kernel    <<<NPOI, 256>>>();
    setup_kernel   <<<1, 256>>>(dist, seq, ids);
    deg_kernel     <<<dim3(NPOI / 256, NB), 256>>>();
    y0t_kernel     <<<dim3(NPOI / 64, NB), 256>>>(poi);
    gemm1_mma_kernel<<<dim3(NPOI / MT, NB), 256, SMEM_TOT>>>();
    gemm2_kernel   <<<dim3(NPOS / 32, NB, KC), 256>>>();
    finalize_kernel<<<(NB * NPOS * DD) / 256, 256>>>(poi, out);
}

// round 6
// speedup vs baseline: 2.8838x; 1.3850x over previous
#include <cuda_runtime.h>
#include <cuda_fp16.h>
#include <cstdint>
#include <cstddef>

#define NPOI 4096
#define DD   64
#define NB   8
#define DAYS 4
#define LL   64
#define NDROWS 32
#define NPOS   256
#define NINT 101
#define KC   4
#define MT   128
#define KT   64
#define NC   (NPOI/KT)
#define BUF_BYTES 24576            /* A 16K + B 8K */
#define LUT_OFF   (2*BUF_BYTES)    /* 49152 */
#define SMEM_TOT  (LUT_OFF + NINT*32*4)

typedef unsigned long long u64;
typedef unsigned int u32;

__device__ __align__(16) unsigned char g_bk[(size_t)NPOI * NPOI];
__device__ unsigned char g_diag[NPOI];
__device__ int   g_histT[NINT * NPOI];
__device__ float g_lut[NB * NINT];
__device__ float g_cntf[NB * NINT];
__device__ float g_invdeg[NB * NPOI];
__device__ int   g_rows[NB * NPOS];
__device__ float g_Y0[(size_t)NB * NPOI * DD];
__device__ float g_L1[(size_t)NB * NPOI * DD];
__device__ float g_Y1[(size_t)NB * NPOI * DD];
__device__ __align__(16) __half g_Yt[(size_t)NB * DD * NPOI];
__device__ float g_part[(size_t)KC * NB * NPOS * DD];

__device__ __forceinline__ u32 smem_u32(const void* p) {
    u32 a; asm("{ .reg .u64 t; cvta.to.shared.u64 t, %1; cvt.u32.u64 %0, t; }" : "=r"(a) : "l"(p));
    return a;
}
__device__ __forceinline__ u32 swz(u32 o) { return o ^ ((o >> 3) & 0x70); }
__device__ __forceinline__ void ldsm4(u32& r0, u32& r1, u32& r2, u32& r3, u32 a) {
    asm volatile("ldmatrix.sync.aligned.m8n8.x4.shared.b16 {%0,%1,%2,%3}, [%4];"
        : "=r"(r0), "=r"(r1), "=r"(r2), "=r"(r3) : "r"(a));
}
__device__ __forceinline__ void mma16816(float* c, const u32* a, u32 b0, u32 b1) {
    asm volatile("mma.sync.aligned.m16n8k16.row.col.f32.f16.f16.f32 "
        "{%0,%1,%2,%3}, {%4,%5,%6,%7}, {%8,%9}, {%0,%1,%2,%3};"
        : "+f"(c[0]), "+f"(c[1]), "+f"(c[2]), "+f"(c[3])
        : "r"(a[0]), "r"(a[1]), "r"(a[2]), "r"(a[3]), "r"(b0), "r"(b1));
}

__global__ __launch_bounds__(256) void bucket_kernel(const float* __restrict__ dist) {
    size_t i = ((size_t)blockIdx.x * 256 + threadIdx.x) * 4;
    float4 v = *(const float4*)(dist + i);
    uchar4 o;
    o.x = (unsigned char)min(100, (int)floorf(v.x * 2.0f) + 1);
    o.y = (unsigned char)min(100, (int)floorf(v.y * 2.0f) + 1);
    o.z = (unsigned char)min(100, (int)floorf(v.z * 2.0f) + 1);
    o.w = (unsigned char)min(100, (int)floorf(v.w * 2.0f) + 1);
    *(uchar4*)(g_bk + i) = o;
}

__global__ __launch_bounds__(256) void hist_kernel() {
    __shared__ int sh[NINT];
    int i = blockIdx.x, t = threadIdx.x;
    if (t < NINT) sh[t] = 0;
    __syncthreads();
    const unsigned char* row = g_bk + (size_t)i * NPOI;
    union { uint4 v; unsigned char b[16]; } bv;
    bv.v = *(const uint4*)(row + t * 16);
    #pragma unroll
    for (int m = 0; m < 16; m++) atomicAdd(&sh[bv.b[m]], 1);
    __syncthreads();
    if (t < NINT) g_histT[t * NPOI + i] = sh[t];
    if (t == 0) g_diag[i] = row[i];
}

__global__ __launch_bounds__(256) void setup_kernel(const float* __restrict__ dist,
                                                    const int* __restrict__ seq,
                                                    const int* __restrict__ ids) {
    __shared__ int sord[NDROWS];
    __shared__ int scnt[NB][NINT];
    int t = threadIdx.x;
    if (t < NDROWS) {
        int my = ids[t], pos = 0;
        for (int q = 0; q < NDROWS; q++) {
            int v = ids[q];
            if (v < my || (v == my && q < t)) pos++;
        }
        sord[pos] = t;
    }
    for (int e = t; e < NB * NINT; e += 256) (&scnt[0][0])[e] = 0;
    __syncthreads();
    for (int e = t; e < NB * NPOS; e += 256) {
        int s = e >> 8, pos = e & 255, day = pos >> 6, l = pos & 63;
        g_rows[e] = seq[sord[s * DAYS + day] * LL + l] - 1;
    }
    for (int e = t; e < NB * (LL - 1); e += 256) {
        int s = e / (LL - 1), tt = e % (LL - 1);
        int lrow = sord[s * DAYS + (DAYS - 1)];
        int a = seq[lrow * LL + tt] - 1;
        int b = seq[lrow * LL + tt + 1] - 1;
        float dv = dist[(size_t)a * NPOI + b];
        int idx = (int)ceilf(dv * 2.0f);
        idx = idx < 0 ? 0 : (idx > 100 ? 100 : idx);
        atomicAdd(&scnt[s][idx], 1);
    }
    __syncthreads();
    for (int e = t; e < NB * NINT; e += 256) {
        int cv = (&scnt[0][0])[e];
        g_lut[e]  = (float)cv / 63.0f;
        g_cntf[e] = (float)cv;
    }
}

__global__ __launch_bounds__(256) void deg_kernel() {
    __shared__ float lc[NINT];
    int s = blockIdx.y, t = threadIdx.x;
    if (t < NINT) lc[t] = g_lut[s * NINT + t];
    __syncthreads();
    int i = blockIdx.x * 256 + t;
    float sum = 1.0f - lc[g_diag[i]];
    #pragma unroll 101
    for (int k = 0; k < NINT; k++) sum += lc[k] * (float)g_histT[k * NPOI + i];
    g_invdeg[s * NPOI + i] = 1.0f / sqrtf(fmaxf(sum, 1e-24f));
}

// Y0 = poi_emb/deg (fp32) + transposed fp16 copy for tensor cores
__global__ __launch_bounds__(256) void y0t_kernel(const float* __restrict__ poi) {
    __shared__ float ts[64][65];
    int s = blockIdx.y, jbase = blockIdx.x * 64, t = threadIdx.x;
    #pragma unroll
    for (int r = 0; r < 16; r++) {
        int idx = r * 256 + t;
        int jl = idx >> 6, d = idx & 63;
        int j = jbase + jl;
        float y = poi[(size_t)(j + 1) * DD + d] * g_invdeg[s * NPOI + j];
        g_Y0[((size_t)s * NPOI + j) * DD + d] = y;
        ts[jl][d] = y;
    }
    __syncthreads();
    #pragma unroll
    for (int r = 0; r < 16; r++) {
        int idx = r * 256 + t;
        int d = idx >> 6, jl = idx & 63;
        g_Yt[((size_t)s * DD + d) * NPOI + jbase + jl] = __float2half(ts[jl][d]);
    }
}

// layer-1: C[128x64] = CNT @ Y^T via fp16 mma.sync, fp32 accum, double-buffered.
extern __shared__ __align__(1024) char dsm[];
__global__ __launch_bounds__(256) void gemm1_mma_kernel() {
    const int t = threadIdx.x, wid = t >> 5, lane = t & 31;
    const int s = blockIdx.y;
    const int rowbase = blockIdx.x * MT;
    u32* lutb = (u32*)(dsm + LUT_OFF);     // [NINT][32] bank-replicated fp16 bits
    const u32 base_u = smem_u32(dsm);

    for (int e = t; e < NINT * 32; e += 256) {
        __half h = __float2half(g_cntf[s * NINT + (e >> 5)]);
        lutb[(e >> 5) * 32 + (e & 31)] = (u32)*(unsigned short*)&h;
    }
    __syncthreads();
    const u32* mylut = lutb + lane;

    // producer mapping
    const int pm = t >> 1, ph = t & 1;            // A: row 0..127, k-half(32 bytes)
    const int bd = t >> 2, bq = t & 3;            // B: d-row 0..63, chunk 0..3 (+4)
    const unsigned char* gA = g_bk + (size_t)(rowbase + pm) * NPOI + ph * 32;
    const __half* gBrow = g_Yt + ((size_t)s * DD + bd) * NPOI;
    // each full byte-offset swizzled BEFORE use (R5 bug: swizzle-then-add corrupts bits[6:4])
    u32 aaddr[2][2];
    #pragma unroll
    for (int u2 = 0; u2 < 2; u2++)
        #pragma unroll
        for (int hq = 0; hq < 2; hq++)
            aaddr[u2][hq] = swz((u32)(pm * 128 + ph * 64 + u2 * 32 + hq * 16));
    const u32 boff0 = swz((u32)(bd * 128 + bq * 16));
    const u32 boff1 = swz((u32)(bd * 128 + (bq + 4) * 16));

    // consumer mapping: 4 warps along M(32 rows), 2 along N(32 cols)
    const int wm = wid & 3, wn = wid >> 2;
    float acc[2][4][4];
    #pragma unroll
    for (int a = 0; a < 2; a++)
        #pragma unroll
        for (int b = 0; b < 4; b++)
            #pragma unroll
            for (int c = 0; c < 4; c++) acc[a][b][c] = 0.0f;

    const u32 arow = (u32)((wm * 32 + (lane & 15)) * 128 + (lane >> 4) * 16);
    const u32 brow = (u32)((wn * 32 + (lane & 15)) * 128 + (lane >> 4) * 16);

    uint4 pa[2], pb[2];
    pa[0] = *(const uint4*)(gA);      pa[1] = *(const uint4*)(gA + 16);
    pb[0] = *(const uint4*)(gBrow + bq * 8);
    pb[1] = *(const uint4*)(gBrow + (bq + 4) * 8);

    // store chunk 0 into buf 0
    {
        char* Ab = dsm; char* Bb = dsm + 16384;
        #pragma unroll
        for (int u2 = 0; u2 < 2; u2++) {
            union { uint4 v; unsigned char b[16]; } q; q.v = pa[u2];
            #pragma unroll
            for (int hq = 0; hq < 2; hq++) {
                uint4 o;
                o.x = mylut[q.b[hq*8+0]*32] | (mylut[q.b[hq*8+1]*32] << 16);
                o.y = mylut[q.b[hq*8+2]*32] | (mylut[q.b[hq*8+3]*32] << 16);
                o.z = mylut[q.b[hq*8+4]*32] | (mylut[q.b[hq*8+5]*32] << 16);
                o.w = mylut[q.b[hq*8+6]*32] | (mylut[q.b[hq*8+7]*32] << 16);
                *(uint4*)(Ab + aaddr[u2][hq]) = o;
            }
        }
        *(uint4*)(Bb + boff0) = pb[0];
        *(uint4*)(Bb + boff1) = pb[1];
    }
    __syncthreads();

    for (int c = 0; c < NC; c++) {
        const u32 bufo = (u32)(c & 1) * BUF_BYTES;
        if (c + 1 < NC) {
            int kb = (c + 1) * KT;
            pa[0] = *(const uint4*)(gA + kb);  pa[1] = *(const uint4*)(gA + kb + 16);
            pb[0] = *(const uint4*)(gBrow + kb + bq * 8);
            pb[1] = *(const uint4*)(gBrow + kb + (bq + 4) * 8);
        }
        // --- MMA on current buffer ---
        const u32 Ab_u = base_u + bufo, Bb_u = base_u + bufo + 16384;
        #pragma unroll
        for (int ks = 0; ks < 2; ks++) {
            #pragma unroll
            for (int kh = 0; kh < 2; kh++) {
                const u32 kby = (u32)((ks * 2 + kh) * 32); // 16 fp16 = 32 B
                u32 afr[2][4];
                #pragma unroll
                for (int mi = 0; mi < 2; mi++)
                    ldsm4(afr[mi][0], afr[mi][1], afr[mi][2], afr[mi][3],
                          Ab_u + swz(arow + mi * 16 * 128 + kby));
                #pragma unroll
                for (int ni2 = 0; ni2 < 2; ni2++) {
                    u32 r0, r1, r2, r3;
                    ldsm4(r0, r1, r2, r3, Bb_u + swz(brow + ni2 * 16 * 128 + kby));
                    #pragma unroll
                    for (int mi = 0; mi < 2; mi++) {
                        mma16816(acc[mi][ni2 * 2],     afr[mi], r0, r2);
                        mma16816(acc[mi][ni2 * 2 + 1], afr[mi], r1, r3);
                    }
                }
            }
        }
        // --- store next chunk into other buffer ---
        if (c + 1 < NC) {
            char* Ab = dsm + ((c + 1) & 1) * BUF_BYTES;
            char* Bb = Ab + 16384;
            #pragma unroll
            for (int u2 = 0; u2 < 2; u2++) {
                union { uint4 v; unsigned char b[16]; } q; q.v = pa[u2];
                #pragma unroll
                for (int hq = 0; hq < 2; hq++) {
                    uint4 o;
                    o.x = mylut[q.b[hq*8+0]*32] | (mylut[q.b[hq*8+1]*32] << 16);
                    o.y = mylut[q.b[hq*8+2]*32] | (mylut[q.b[hq*8+3]*32] << 16);
                    o.z = mylut[q.b[hq*8+4]*32] | (mylut[q.b[hq*8+5]*32] << 16);
                    o.w = mylut[q.b[hq*8+6]*32] | (mylut[q.b[hq*8+7]*32] << 16);
                    *(uint4*)(Ab + aaddr[u2][hq]) = o;
                }
            }
            *(uint4*)(Bb + boff0) = pb[0];
            *(uint4*)(Bb + boff1) = pb[1];
        }
        __syncthreads();
    }

    // --- epilogue: /63, diag fix, tanh; write L1, Y1 ---
    #pragma unroll
    for (int mi = 0; mi < 2; mi++) {
        #pragma unroll
        for (int e2 = 0; e2 < 2; e2++) {
            int i = rowbase + wm * 32 + mi * 16 + (lane >> 2) + e2 * 8;
            float idg = g_invdeg[s * NPOI + i];
            float dterm = 1.0f - g_lut[s * NINT + g_diag[i]];
            const float* y0r = g_Y0 + ((size_t)s * NPOI + i) * DD;
            float* l1r = g_L1 + ((size_t)s * NPOI + i) * DD;
            float* y1r = g_Y1 + ((size_t)s * NPOI + i) * DD;
            #pragma unroll
            for (int ni = 0; ni < 4; ni++) {
                #pragma unroll
                for (int e1 = 0; e1 < 2; e1++) {
                    int d = wn * 32 + ni * 8 + (lane & 3) * 2 + e1;
                    float cf = acc[mi][ni][e2 * 2 + e1] * (1.0f / 63.0f);
                    float l1 = tanhf(idg * (cf + dterm * y0r[d]));
                    l1r[d] = l1;
                    y1r[d] = l1 * idg;
                }
            }
        }
    }
}

__global__ __launch_bounds__(256) void gemm2_kernel() {
    __shared__ float Asm[64][32];
    __shared__ float Ysm[64][64];
    __shared__ float slut[NINT + 3];
    __shared__ int srows[32];
    int pb = blockIdx.x, s = blockIdx.y, kc = blockIdx.z, t = threadIdx.x;
    int tx = t & 15, ty = t >> 4;
    if (t < NINT) slut[t] = g_lut[s * NINT + t];
    if (t < 32)  srows[t] = g_rows[s * NPOS + pb * 32 + t];
    __syncthreads();
    const float* Yg = g_Y1 + (size_t)s * NPOI * DD;
    float acc[2][4] = {};
    int ra = t >> 3, kq = (t & 7) * 8;
    const unsigned char* bkp = g_bk + (size_t)srows[ra] * NPOI + kq;
    int k0 = kc * (NPOI / KC), k1 = k0 + (NPOI / KC);
    for (int kb = k0; kb < k1; kb += 64) {
        union { uint2 v; unsigned char b[8]; } bv;
        bv.v = *(const uint2*)(bkp + kb);
        #pragma unroll
        for (int m = 0; m < 8; m++) Asm[kq + m][ra] = slut[bv.b[m]];
        #pragma unroll
        for (int m = 0; m < 4; m++) {
            int idx = t + m * 256;
            int k2 = idx >> 4, d4 = (idx & 15) * 4;
            *(float4*)&Ysm[k2][d4] = *(const float4*)(Yg + (size_t)(kb + k2) * DD + d4);
        }
        __syncthreads();
        #pragma unroll 16
        for (int k = 0; k < 64; k++) {
            float a0 = Asm[k][ty * 2], a1 = Asm[k][ty * 2 + 1];
            float4 y = *(const float4*)&Ysm[k][tx * 4];
            acc[0][0] += a0 * y.x; acc[0][1] += a0 * y.y;
            acc[0][2] += a0 * y.z; acc[0][3] += a0 * y.w;
            acc[1][0] += a1 * y.x; acc[1][1] += a1 * y.y;
            acc[1][2] += a1 * y.z; acc[1][3] += a1 * y.w;
        }
        __syncthreads();
    }
    #pragma unroll
    for (int r = 0; r < 2; r++) {
        int pos = pb * 32 + ty * 2 + r;
        #pragma unroll
        for (int c = 0; c < 4; c++)
            g_part[(((size_t)kc * NB + s) * NPOS + pos) * DD + tx * 4 + c] = acc[r][c];
    }
}

__global__ __launch_bounds__(256) void finalize_kernel(const float* __restrict__ poi,
                                                       float* __restrict__ out) {
    int e = blockIdx.x * 256 + threadIdx.x;
    int d = e & 63, pl = e >> 6, pos = pl & 255, s = pl >> 8;
    int r = g_rows[s * NPOS + pos];
    float acc = 0.0f;
    #pragma unroll
    for (int kc = 0; kc < KC; kc++)
        acc += g_part[(((size_t)kc * NB + s) * NPOS + pos) * DD + d];
    float idg = g_invdeg[s * NPOI + r];
    float dterm = 1.0f - g_lut[s * NINT + g_diag[r]];
    size_t off = ((size_t)s * NPOI + r) * DD + d;
    float l2 = tanhf(idg * (acc + dterm * g_Y1[off]));
    float v = 8.0f * (poi[(size_t)(r + 1) * DD + d] + g_L1[off] + l2);
    int day = pos >> 6, l = pos & 63;
    out[(((size_t)(s * DAYS + day)) * LL + l) * DD + d] = v;
}

extern "C" void kernel_launch(void* const* d_in, const int* in_sizes, int n_in,
                              void* d_out, int out_size) {
    (void)in_sizes; (void)n_in; (void)out_size;
    const float* poi  = (const float*)d_in[0];
    const float* dist = (const float*)d_in[1];
    const int*   seq  = (const int*)d_in[2];
    const int*   ids  = (const int*)d_in[3];
    float* out = (float*)d_out;

    cudaFuncSetAttribute(gemm1_mma_kernel, cudaFuncAttributeMaxDynamicSharedMemorySize, SMEM_TOT);

    bucket_kernel  <<<(NPOI * NPOI) / 1024, 256>>>(dist);
    hist_kernel    <<<NPOI, 256>>>();
    setup_kernel   <<<1, 256>>>(dist, seq, ids);
    deg_kernel     <<<dim3(NPOI / 256, NB), 256>>>();
    y0t_kernel     <<<dim3(NPOI / 64, NB), 256>>>(poi);
    gemm1_mma_kernel<<<dim3(NPOI / MT, NB), 256, SMEM_TOT>>>();
    gemm2_kernel   <<<dim3(NPOS / 32, NB, KC), 256>>>();
    finalize_kernel<<<(NB * NPOS * DD) / 256, 256>>>(poi, out);
}

// round 8
// speedup vs baseline: 3.5709x; 1.2383x over previous
#include <cuda_runtime.h>
#include <cuda_fp16.h>
#include <cstdint>
#include <cstddef>

#define NPOI 4096
#define DD   64
#define NB   8
#define DAYS 4
#define LL   64
#define NDROWS 32
#define NPOS   256
#define NINT 101
#define KC   4
#define MT   128
#define KT   64
#define NC   (NPOI/KT)
#define NC2  16
#define BUF_BYTES 24576
#define LUT_OFF   (2*BUF_BYTES)
#define LUT_BYTES (NINT*32*4)
#define SMEM_TOT  (LUT_OFF + 2*LUT_BYTES)
#define SMEM_TOT2 (LUT_OFF + 2*LUT_BYTES + 512)

typedef unsigned long long u64;
typedef unsigned int u32;

__device__ __align__(16) unsigned char g_bk[(size_t)NPOI * NPOI];
__device__ unsigned char g_diag[NPOI];
__device__ int   g_histT[NINT * NPOI];
__device__ float g_lut[NB * NINT];
__device__ float g_cntf[NB * NINT];
__device__ float g_invdeg[NB * NPOI];
__device__ int   g_rows[NB * NPOS];
__device__ float g_Y0[(size_t)NB * NPOI * DD];
__device__ float g_L1[(size_t)NB * NPOI * DD];
__device__ float g_Y1[(size_t)NB * NPOI * DD];
__device__ __align__(16) __half g_Yt[(size_t)NB * DD * NPOI];
__device__ __align__(16) __half g_Y1t[(size_t)NB * DD * NPOI];
__device__ float g_part[(size_t)KC * NB * NPOS * DD];

__device__ __forceinline__ u32 smem_u32(const void* p) {
    u32 a; asm("{ .reg .u64 t; cvta.to.shared.u64 t, %1; cvt.u32.u64 %0, t; }" : "=r"(a) : "l"(p));
    return a;
}
__device__ __forceinline__ u32 swz(u32 o) { return o ^ ((o >> 3) & 0x70); }
__device__ __forceinline__ void ldsm4(u32& r0, u32& r1, u32& r2, u32& r3, u32 a) {
    asm volatile("ldmatrix.sync.aligned.m8n8.x4.shared.b16 {%0,%1,%2,%3}, [%4];"
        : "=r"(r0), "=r"(r1), "=r"(r2), "=r"(r3) : "r"(a));
}
__device__ __forceinline__ void mma16816(float* c, const u32* a, u32 b0, u32 b1) {
    asm volatile("mma.sync.aligned.m16n8k16.row.col.f32.f16.f16.f32 "
        "{%0,%1,%2,%3}, {%4,%5,%6,%7}, {%8,%9}, {%0,%1,%2,%3};"
        : "+f"(c[0]), "+f"(c[1]), "+f"(c[2]), "+f"(c[3])
        : "r"(a[0]), "r"(a[1]), "r"(a[2]), "r"(a[3]), "r"(b0), "r"(b1));
}
#define CPA16(dst, src) asm volatile("cp.async.cg.shared.global [%0], [%1], 16;" :: "r"(dst), "l"(src))
#define CPCOMMIT()      asm volatile("cp.async.commit_group;")
#define CPWAIT0()       asm volatile("cp.async.wait_group 0;")

__device__ __forceinline__ void conv_store_A(const u32* lo, const u32* hi,
                                             const uint4* pa, char* Ab, const u32* aaddr) {
    #pragma unroll
    for (int u2 = 0; u2 < 2; u2++) {
        union { uint4 v; unsigned char b[16]; } q; q.v = pa[u2];
        #pragma unroll
        for (int hq = 0; hq < 2; hq++) {
            uint4 o;
            o.x = lo[q.b[hq*8+0]*32] | hi[q.b[hq*8+1]*32];
            o.y = lo[q.b[hq*8+2]*32] | hi[q.b[hq*8+3]*32];
            o.z = lo[q.b[hq*8+4]*32] | hi[q.b[hq*8+5]*32];
            o.w = lo[q.b[hq*8+6]*32] | hi[q.b[hq*8+7]*32];
            *(uint4*)(Ab + aaddr[u2*2+hq]) = o;
        }
    }
}

__device__ __forceinline__ void mma_chunk(u32 Ab_u, u32 Bb_u, u32 arow, u32 brow,
                                          float (&acc)[2][4][4]) {
    #pragma unroll
    for (int kk = 0; kk < 4; kk++) {
        const u32 kby = (u32)(kk * 32);
        u32 afr[2][4];
        #pragma unroll
        for (int mi = 0; mi < 2; mi++)
            ldsm4(afr[mi][0], afr[mi][1], afr[mi][2], afr[mi][3],
                  Ab_u + swz(arow + mi * 16 * 128 + kby));
        #pragma unroll
        for (int ni2 = 0; ni2 < 2; ni2++) {
            u32 r0, r1, r2, r3;
            ldsm4(r0, r1, r2, r3, Bb_u + swz(brow + ni2 * 16 * 128 + kby));
            #pragma unroll
            for (int mi = 0; mi < 2; mi++) {
                mma16816(acc[mi][ni2 * 2],     afr[mi], r0, r2);
                mma16816(acc[mi][ni2 * 2 + 1], afr[mi], r1, r3);
            }
        }
    }
}

__global__ __launch_bounds__(256) void bucket_kernel(const float* __restrict__ dist) {
    size_t i = ((size_t)blockIdx.x * 256 + threadIdx.x) * 4;
    float4 v = *(const float4*)(dist + i);
    uchar4 o;
    o.x = (unsigned char)min(100, (int)floorf(v.x * 2.0f) + 1);
    o.y = (unsigned char)min(100, (int)floorf(v.y * 2.0f) + 1);
    o.z = (unsigned char)min(100, (int)floorf(v.z * 2.0f) + 1);
    o.w = (unsigned char)min(100, (int)floorf(v.w * 2.0f) + 1);
    *(uchar4*)(g_bk + i) = o;
}

__global__ __launch_bounds__(256) void hist_kernel() {
    __shared__ int sh[NINT];
    int i = blockIdx.x, t = threadIdx.x;
    if (t < NINT) sh[t] = 0;
    __syncthreads();
    const unsigned char* row = g_bk + (size_t)i * NPOI;
    union { uint4 v; unsigned char b[16]; } bv;
    bv.v = *(const uint4*)(row + t * 16);
    #pragma unroll
    for (int m = 0; m < 16; m++) atomicAdd(&sh[bv.b[m]], 1);
    __syncthreads();
    if (t < NINT) g_histT[t * NPOI + i] = sh[t];
    if (t == 0) g_diag[i] = row[i];
}

__global__ __launch_bounds__(256) void setup_kernel(const float* __restrict__ dist,
                                                    const int* __restrict__ seq,
                                                    const int* __restrict__ ids) {
    __shared__ int sord[NDROWS];
    __shared__ int scnt[NB][NINT];
    int t = threadIdx.x;
    if (t < NDROWS) {
        int my = ids[t], pos = 0;
        for (int q = 0; q < NDROWS; q++) {
            int v = ids[q];
            if (v < my || (v == my && q < t)) pos++;
        }
        sord[pos] = t;
    }
    for (int e = t; e < NB * NINT; e += 256) (&scnt[0][0])[e] = 0;
    __syncthreads();
    for (int e = t; e < NB * NPOS; e += 256) {
        int s = e >> 8, pos = e & 255, day = pos >> 6, l = pos & 63;
        g_rows[e] = seq[sord[s * DAYS + day] * LL + l] - 1;
    }
    for (int e = t; e < NB * (LL - 1); e += 256) {
        int s = e / (LL - 1), tt = e % (LL - 1);
        int lrow = sord[s * DAYS + (DAYS - 1)];
        int a = seq[lrow * LL + tt] - 1;
        int b = seq[lrow * LL + tt + 1] - 1;
        float dv = dist[(size_t)a * NPOI + b];
        int idx = (int)ceilf(dv * 2.0f);
        idx = idx < 0 ? 0 : (idx > 100 ? 100 : idx);
        atomicAdd(&scnt[s][idx], 1);
    }
    __syncthreads();
    for (int e = t; e < NB * NINT; e += 256) {
        int cv = (&scnt[0][0])[e];
        g_lut[e]  = (float)cv / 63.0f;
        g_cntf[e] = (float)cv;
    }
}

__global__ __launch_bounds__(256) void deg_kernel() {
    __shared__ float lc[NINT];
    int s = blockIdx.y, t = threadIdx.x;
    if (t < NINT) lc[t] = g_lut[s * NINT + t];
    __syncthreads();
    int i = blockIdx.x * 256 + t;
    float sum = 1.0f - lc[g_diag[i]];
    #pragma unroll 101
    for (int k = 0; k < NINT; k++) sum += lc[k] * (float)g_histT[k * NPOI + i];
    g_invdeg[s * NPOI + i] = 1.0f / sqrtf(fmaxf(sum, 1e-24f));
}

__global__ __launch_bounds__(256) void y0t_kernel(const float* __restrict__ poi) {
    __shared__ float ts[64][65];
    int s = blockIdx.y, jbase = blockIdx.x * 64, t = threadIdx.x;
    #pragma unroll
    for (int r = 0; r < 16; r++) {
        int idx = r * 256 + t;
        int jl = idx >> 6, d = idx & 63;
        int j = jbase + jl;
        float y = poi[(size_t)(j + 1) * DD + d] * g_invdeg[s * NPOI + j];
        g_Y0[((size_t)s * NPOI + j) * DD + d] = y;
        ts[jl][d] = y;
    }
    __syncthreads();
    #pragma unroll
    for (int r = 0; r < 16; r++) {
        int idx = r * 256 + t;
        int d = idx >> 6, jl = idx & 63;
        g_Yt[((size_t)s * DD + d) * NPOI + jbase + jl] = __float2half(ts[jl][d]);
    }
}

__global__ __launch_bounds__(256) void y1t_kernel() {
    __shared__ float ts[64][65];
    int s = blockIdx.y, jbase = blockIdx.x * 64, t = threadIdx.x;
    #pragma unroll
    for (int r = 0; r < 16; r++) {
        int idx = r * 256 + t;
        int jl = idx >> 6, d = idx & 63;
        ts[jl][d] = g_Y1[((size_t)s * NPOI + jbase + jl) * DD + d];
    }
    __syncthreads();
    #pragma unroll
    for (int r = 0; r < 16; r++) {
        int idx = r * 256 + t;
        int d = idx >> 6, jl = idx & 63;
        g_Y1t[((size_t)s * DD + d) * NPOI + jbase + jl] = __float2half(ts[jl][d]);
    }
}

extern __shared__ __align__(1024) char dsm[];
__global__ __launch_bounds__(256, 2) void gemm1_mma_kernel() {
    const int t = threadIdx.x, wid = t >> 5, lane = t & 31;
    const int s = blockIdx.y;
    const int rowbase = blockIdx.x * MT;
    u32* lutlo = (u32*)(dsm + LUT_OFF);
    u32* luthi = (u32*)(dsm + LUT_OFF + LUT_BYTES);
    const u32 base_u = smem_u32(dsm);

    for (int e = t; e < NINT * 32; e += 256) {
        __half h = __float2half(g_cntf[s * NINT + (e >> 5)]);
        u32 bits = (u32)*(unsigned short*)&h;
        lutlo[e] = bits;
        luthi[e] = bits << 16;
    }
    __syncthreads();
    const u32* mlo = lutlo + lane;
    const u32* mhi = luthi + lane;

    const int pm = t >> 1, ph = t & 1;
    const int bd = t >> 2, bq = t & 3;
    const unsigned char* gA = g_bk + (size_t)(rowbase + pm) * NPOI + ph * 32;
    const __half* gBrow = g_Yt + ((size_t)s * DD + bd) * NPOI;
    u32 aaddr[4];
    #pragma unroll
    for (int u2 = 0; u2 < 2; u2++)
        #pragma unroll
        for (int hq = 0; hq < 2; hq++)
            aaddr[u2*2+hq] = swz((u32)(pm * 128 + ph * 64 + u2 * 32 + hq * 16));
    const u32 boff0 = swz((u32)(bd * 128 + bq * 16));
    const u32 boff1 = swz((u32)(bd * 128 + (bq + 4) * 16));

    const int wm = wid & 3, wn = wid >> 2;
    float acc[2][4][4];
    #pragma unroll
    for (int a = 0; a < 2; a++)
        #pragma unroll
        for (int b = 0; b < 4; b++)
            #pragma unroll
            for (int c = 0; c < 4; c++) acc[a][b][c] = 0.0f;

    const u32 arow = (u32)((wm * 32 + (lane & 15)) * 128 + (lane >> 4) * 16);
    const u32 brow = (u32)((wn * 32 + (lane & 15)) * 128 + (lane >> 4) * 16);

    uint4 pa[2];
    pa[0] = *(const uint4*)(gA);  pa[1] = *(const uint4*)(gA + 16);
    CPA16(base_u + 16384 + boff0, gBrow + bq * 8);
    CPA16(base_u + 16384 + boff1, gBrow + (bq + 4) * 8);
    CPCOMMIT();
    conv_store_A(mlo, mhi, pa, dsm, aaddr);
    CPWAIT0();
    __syncthreads();

    for (int c = 0; c < NC; c++) {
        const u32 bufo = (u32)(c & 1) * BUF_BYTES;
        const u32 nbufo = (u32)((c + 1) & 1) * BUF_BYTES;
        if (c + 1 < NC) {
            int kb = (c + 1) * KT;
            pa[0] = *(const uint4*)(gA + kb);  pa[1] = *(const uint4*)(gA + kb + 16);
            CPA16(base_u + nbufo + 16384 + boff0, gBrow + kb + bq * 8);
            CPA16(base_u + nbufo + 16384 + boff1, gBrow + kb + (bq + 4) * 8);
            CPCOMMIT();
        }
        mma_chunk(base_u + bufo, base_u + bufo + 16384, arow, brow, acc);
        if (c + 1 < NC) conv_store_A(mlo, mhi, pa, dsm + nbufo, aaddr);
        CPWAIT0();
        __syncthreads();
    }

    #pragma unroll
    for (int mi = 0; mi < 2; mi++) {
        #pragma unroll
        for (int e2 = 0; e2 < 2; e2++) {
            int i = rowbase + wm * 32 + mi * 16 + (lane >> 2) + e2 * 8;
            float idg = g_invdeg[s * NPOI + i];
            float dterm = 1.0f - g_lut[s * NINT + g_diag[i]];
            const float* y0r = g_Y0 + ((size_t)s * NPOI + i) * DD;
            float* l1r = g_L1 + ((size_t)s * NPOI + i) * DD;
            float* y1r = g_Y1 + ((size_t)s * NPOI + i) * DD;
            #pragma unroll
            for (int ni = 0; ni < 4; ni++) {
                #pragma unroll
                for (int e1 = 0; e1 < 2; e1++) {
                    int d = wn * 32 + ni * 8 + (lane & 3) * 2 + e1;
                    float cf = acc[mi][ni][e2 * 2 + e1] * (1.0f / 63.0f);
                    float l1 = tanhf(idg * (cf + dterm * y0r[d]));
                    l1r[d] = l1;
                    y1r[d] = l1 * idg;
                }
            }
        }
    }
}

__global__ __launch_bounds__(256, 2) void gemm2_mma_kernel() {
    const int t = threadIdx.x, wid = t >> 5, lane = t & 31;
    const int pb = blockIdx.x;
    const int s  = blockIdx.y;
    const int kc = blockIdx.z;
    u32* lutlo = (u32*)(dsm + LUT_OFF);
    u32* luthi = (u32*)(dsm + LUT_OFF + LUT_BYTES);
    int* srows = (int*)(dsm + LUT_OFF + 2 * LUT_BYTES);
    const u32 base_u = smem_u32(dsm);

    for (int e = t; e < NINT * 32; e += 256) {
        __half h = __float2half(g_cntf[s * NINT + (e >> 5)]);
        u32 bits = (u32)*(unsigned short*)&h;
        lutlo[e] = bits;
        luthi[e] = bits << 16;
    }
    if (t < 128) srows[t] = g_rows[s * NPOS + pb * 128 + t];
    __syncthreads();
    const u32* mlo = lutlo + lane;
    const u32* mhi = luthi + lane;

    const int pm = t >> 1, ph = t & 1;
    const int bd = t >> 2, bq = t & 3;
    const int kbase = kc * (NPOI / KC);
    const unsigned char* gA = g_bk + (size_t)srows[pm] * NPOI + kbase + ph * 32;
    const __half* gBrow = g_Y1t + ((size_t)s * DD + bd) * NPOI + kbase;
    u32 aaddr[4];
    #pragma unroll
    for (int u2 = 0; u2 < 2; u2++)
        #pragma unroll
        for (int hq = 0; hq < 2; hq++)
            aaddr[u2*2+hq] = swz((u32)(pm * 128 + ph * 64 + u2 * 32 + hq * 16));
    const u32 boff0 = swz((u32)(bd * 128 + bq * 16));
    const u32 boff1 = swz((u32)(bd * 128 + (bq + 4) * 16));

    const int wm = wid & 3, wn = wid >> 2;
    float acc[2][4][4];
    #pragma unroll
    for (int a = 0; a < 2; a++)
        #pragma unroll
        for (int b = 0; b < 4; b++)
            #pragma unroll
            for (int c = 0; c < 4; c++) acc[a][b][c] = 0.0f;

    const u32 arow = (u32)((wm * 32 + (lane & 15)) * 128 + (lane >> 4) * 16);
    const u32 brow = (u32)((wn * 32 + (lane & 15)) * 128 + (lane >> 4) * 16);

    uint4 pa[2];
    pa[0] = *(const uint4*)(gA);  pa[1] = *(const uint4*)(gA + 16);
    CPA16(base_u + 16384 + boff0, gBrow + bq * 8);
    CPA16(base_u + 16384 + boff1, gBrow + (bq + 4) * 8);
    CPCOMMIT();
    conv_store_A(mlo, mhi, pa, dsm, aaddr);
    CPWAIT0();
    __syncthreads();

    for (int c = 0; c < NC2; c++) {
        const u32 bufo = (u32)(c & 1) * BUF_BYTES;
        const u32 nbufo = (u32)((c + 1) & 1) * BUF_BYTES;
        if (c + 1 < NC2) {
            int kb = (c + 1) * KT;
            pa[0] = *(const uint4*)(gA + kb);  pa[1] = *(const uint4*)(gA + kb + 16);
            CPA16(base_u + nbufo + 16384 + boff0, gBrow + kb + bq * 8);
            CPA16(base_u + nbufo + 16384 + boff1, gBrow + kb + (bq + 4) * 8);
            CPCOMMIT();
        }
        mma_chunk(base_u + bufo, base_u + bufo + 16384, arow, brow, acc);
        if (c + 1 < NC2) conv_store_A(mlo, mhi, pa, dsm + nbufo, aaddr);
        CPWAIT0();
        __syncthreads();
    }

    float* pdst = g_part + ((size_t)kc * NB + s) * NPOS * DD + (size_t)pb * 128 * DD;
    #pragma unroll
    for (int mi = 0; mi < 2; mi++) {
        #pragma unroll
        for (int e2 = 0; e2 < 2; e2++) {
            int pl = wm * 32 + mi * 16 + (lane >> 2) + e2 * 8;
            #pragma unroll
            for (int ni = 0; ni < 4; ni++) {
                int d = wn * 32 + ni * 8 + (lane & 3) * 2;
                *(float2*)(pdst + pl * DD + d) =
                    make_float2(acc[mi][ni][e2 * 2], acc[mi][ni][e2 * 2 + 1]);
            }
        }
    }
}

__global__ __launch_bounds__(256) void finalize_kernel(const float* __restrict__ poi,
                                                       float* __restrict__ out) {
    int e = blockIdx.x * 256 + threadIdx.x;
    int d = e & 63, pl = e >> 6, pos = pl & 255, s = pl >> 8;
    int r = g_rows[s * NPOS + pos];
    float acc = 0.0f;
    #pragma unroll
    for (int kc = 0; kc < KC; kc++)
        acc += g_part[(((size_t)kc * NB + s) * NPOS + pos) * DD + d];
    acc *= (1.0f / 63.0f);   // gemm2 now accumulates raw counts (R7 bug: this was missing)
    float idg = g_invdeg[s * NPOI + r];
    float dterm = 1.0f - g_lut[s * NINT + g_diag[r]];
    size_t off = ((size_t)s * NPOI + r) * DD + d;
    float l2 = tanhf(idg * (acc + dterm * g_Y1[off]));
    float v = 8.0f * (poi[(size_t)(r + 1) * DD + d] + g_L1[off] + l2);
    int day = pos >> 6, l = pos & 63;
    out[(((size_t)(s * DAYS + day)) * LL + l) * DD + d] = v;
}

extern "C" void kernel_launch(void* const* d_in, const int* in_sizes, int n_in,
                              void* d_out, int out_size) {
    (void)in_sizes; (void)n_in; (void)out_size;
    const float* poi  = (const float*)d_in[0];
    const float* dist = (const float*)d_in[1];
    const int*   seq  = (const int*)d_in[2];
    const int*   ids  = (const int*)d_in[3];
    float* out = (float*)d_out;

    cudaFuncSetAttribute(gemm1_mma_kernel, cudaFuncAttributeMaxDynamicSharedMemorySize, SMEM_TOT);
    cudaFuncSetAttribute(gemm2_mma_kernel, cudaFuncAttributeMaxDynamicSharedMemorySize, SMEM_TOT2);

    bucket_kernel  <<<(NPOI * NPOI) / 1024, 256>>>(dist);
    hist_kernel    <<<NPOI, 256>>>();
    setup_kernel   <<<1, 256>>>(dist, seq, ids);
    deg_kernel     <<<dim3(NPOI / 256, NB), 256>>>();
    y0t_kernel     <<<dim3(NPOI / 64, NB), 256>>>(poi);
    gemm1_mma_kernel<<<dim3(NPOI / MT, NB), 256, SMEM_TOT>>>();
    y1t_kernel     <<<dim3(NPOI / 64, NB), 256>>>();
    gemm2_mma_kernel<<<dim3(2, NB, KC), 256, SMEM_TOT2>>>();
    finalize_kernel<<<(NB * NPOS * DD) / 256, 256>>>(poi, out);
}